// round 3
// baseline (speedup 1.0000x reference)
#include <cuda_runtime.h>
#include <cstdint>

// Problem constants
#define NN 64
#define CC 32
#define MM 4000
#define LL 2000
#define DD 16
#define OO 32
#define KK (CC*DD)          // 512
#define CHUNK 128           // k per chunk (4 d-slices)
#define NCHUNK (KK/CHUNK)   // 4
#define KP_PER_CHUNK 64     // k-pairs per chunk

// Shared layout (bytes):
//   As2[2][64 kpair][64 n float2]          row = 512 B       -> 2*32768
//   Bs2[2][64 kpair][32 o float2 + pad]    row = 272 B       -> 2*17408
//   idxs[16]
#define A_ROW 512
#define B_ROW 272
#define A_BUF (KP_PER_CHUNK * A_ROW)     // 32768
#define B_BUF (KP_PER_CHUNK * B_ROW)     // 17408
#define OFF_A0 0
#define OFF_A1 A_BUF
#define OFF_B0 (2 * A_BUF)
#define OFF_B1 (2 * A_BUF + B_BUF)
#define OFF_IDX (2 * A_BUF + 2 * B_BUF)
#define SMEM_BYTES (OFF_IDX + 64)

// Scratch: x rearranged as xT2[m][cc][n] float2 where element (m,cc,n) =
// (x[n][2cc][m], x[n][2cc+1][m]).  Per m: 2048 floats, [cc*128 + n*2 + h].
__device__ float g_xT2[(size_t)MM * NN * CC];

// ---------------------------------------------------------------------------
// Kernel 1: build xT2.  Block handles 8 m x 8 c x 64 n.
// grid (MM/8, CC/8), 128 threads.
// ---------------------------------------------------------------------------
__global__ void build_xT2_kernel(const float* __restrict__ x) {
    __shared__ float s[8 * 8 * 65];      // s[(ci*8+mi)*65 + n]
    int m0 = blockIdx.x * 8;
    int c0 = blockIdx.y * 8;
    int tid = threadIdx.x;

#pragma unroll
    for (int t = 0; t < 32; t++) {
        int u  = tid + 128 * t;          // u < 4096
        int mi = u & 7;
        int ci = (u >> 3) & 7;
        int n  = u >> 6;
        s[(ci * 8 + mi) * 65 + n] = x[(size_t)(n * CC + c0 + ci) * MM + m0 + mi];
    }
    __syncthreads();
#pragma unroll
    for (int t = 0; t < 32; t++) {
        int u   = tid + 128 * t;
        int h   = u & 1;
        int nn  = (u >> 1) & 63;
        int cci = (u >> 7) & 3;
        int mi  = u >> 9;
        int ci  = 2 * cci + h;
        g_xT2[(size_t)(m0 + mi) * (NN * CC) + ((c0 >> 1) + cci) * 128 + nn * 2 + h]
            = s[(ci * 8 + mi) * 65 + nn];
    }
}

// ---------------------------------------------------------------------------
// Kernel 2: per-l gather-GEMM, FFMA2, k-pair-major smem layouts, double-buffered.
// ---------------------------------------------------------------------------
#define FMA2(c_, a_, b_) \
    asm("fma.rn.f32x2 %0, %1, %2, %3;" : "=l"(c_) : "l"(a_), "l"(b_), "l"(c_))

#define CP_ASYNC16(dst_, src_) \
    asm volatile("cp.async.cg.shared.global [%0], [%1], 16;" :: "r"(dst_), "l"(src_))

__global__ __launch_bounds__(128, 2)
void embed_bigraph_kernel(const float* __restrict__ W,
                          const float* __restrict__ bias,
                          const int*   __restrict__ idx,
                          float*       __restrict__ out) {
    extern __shared__ char sm[];
    int* idxs = (int*)(sm + OFF_IDX);

    const int l    = blockIdx.x;
    const int tid  = threadIdx.x;
    const int w    = tid >> 5;
    const int lane = tid & 31;
    const int o_grp = lane >> 2;             // 0..7  -> o = o_grp*4 + j
    const int n_grp = lane & 3;              // 0..3  -> n = w*16 + n_grp*4 + i
    const int nb    = w * 16 + n_grp * 4;
    const int ob    = o_grp * 4;

    if (tid < DD) idxs[tid] = idx[l * DD + tid];
    __syncthreads();

    const uint32_t smem_u32 = (uint32_t)__cvta_generic_to_shared(sm);

    // ---- staging helpers ----
    auto stage_A = [&](int ch, int buf) {
        uint32_t dstb = smem_u32 + (buf ? OFF_A1 : OFF_A0);
#pragma unroll
        for (int t = 0; t < 16; t++) {
            int u  = tid + 128 * t;          // u < 2048 (16B units)
            int dd = u >> 9;
            int cc = (u >> 5) & 15;
            int q  = u & 31;
            const float* src = g_xT2 + (size_t)idxs[ch * 4 + dd] * (NN * CC)
                               + cc * 128 + q * 4;
            CP_ASYNC16(dstb + (uint32_t)((dd * 16 + cc) * A_ROW + q * 16), src);
        }
        asm volatile("cp.async.commit_group;" ::: "memory");
    };

    float4 breg[8];
    auto ldg_B = [&](int ch) {
#pragma unroll
        for (int t = 0; t < 8; t++) {
            int p = tid + 128 * t;           // p = o*32 + c
            breg[t] = *reinterpret_cast<const float4*>(
                W + ((size_t)l * 1024 + p) * DD + ch * 4);
        }
    };
    auto sts_B = [&](int buf) {
        char* base = sm + (buf ? OFF_B1 : OFF_B0);
#pragma unroll
        for (int t = 0; t < 8; t++) {
            int p = tid + 128 * t;
            int o = p >> 5, c = p & 31;
            int col = o * 8 + (c & 1) * 4;
            float* r0 = (float*)(base + ((c >> 1)) * B_ROW + col);
            r0[0]                             = breg[t].x;   // dd=0 -> row (c>>1)
            *(float*)((char*)r0 + 16 * B_ROW) = breg[t].y;   // dd=1
            *(float*)((char*)r0 + 32 * B_ROW) = breg[t].z;   // dd=2
            *(float*)((char*)r0 + 48 * B_ROW) = breg[t].w;   // dd=3
        }
    };

    // ---- prologue: stage chunk 0 ----
    stage_A(0, 0);
    ldg_B(0);
    sts_B(0);
    asm volatile("cp.async.wait_group 0;" ::: "memory");
    __syncthreads();

    unsigned long long acc[16];
#pragma unroll
    for (int i = 0; i < 16; i++) acc[i] = 0ull;

    for (int ch = 0; ch < NCHUNK; ch++) {
        const int s = ch & 1;
        if (ch < NCHUNK - 1) {
            stage_A(ch + 1, s ^ 1);
            ldg_B(ch + 1);
        }

        const char* Ab = sm + (s ? OFF_A1 : OFF_A0) + nb * 8;
        const char* Bb = sm + (s ? OFF_B1 : OFF_B0) + ob * 8;

#pragma unroll 8
        for (int kp = 0; kp < KP_PER_CHUNK; kp++) {
            ulonglong2 a01 = *(const ulonglong2*)(Ab + kp * A_ROW);
            ulonglong2 a23 = *(const ulonglong2*)(Ab + kp * A_ROW + 16);
            ulonglong2 b01 = *(const ulonglong2*)(Bb + kp * B_ROW);
            ulonglong2 b23 = *(const ulonglong2*)(Bb + kp * B_ROW + 16);
            unsigned long long av[4] = {a01.x, a01.y, a23.x, a23.y};
            unsigned long long bv[4] = {b01.x, b01.y, b23.x, b23.y};
#pragma unroll
            for (int i = 0; i < 4; i++)
#pragma unroll
                for (int j = 0; j < 4; j++)
                    FMA2(acc[i * 4 + j], av[i], bv[j]);
        }

        if (ch < NCHUNK - 1) {
            sts_B(s ^ 1);
            asm volatile("cp.async.wait_group 0;" ::: "memory");
            __syncthreads();
        }
    }

    // ---- epilogue: fold f32x2 halves, add bias, scattered store ----
#pragma unroll
    for (int j = 0; j < 4; j++) {
        int o = ob + j;
        float bj = __ldg(bias + l * OO + o);
#pragma unroll
        for (int i = 0; i < 4; i++) {
            int n = nb + i;
            unsigned int lo, hi;
            asm("mov.b64 {%0,%1}, %2;" : "=r"(lo), "=r"(hi) : "l"(acc[i * 4 + j]));
            out[(size_t)n * (OO * LL) + (size_t)o * LL + l]
                = __uint_as_float(lo) + __uint_as_float(hi) + bj;
        }
    }
}

// ---------------------------------------------------------------------------
// Launch
// ---------------------------------------------------------------------------
extern "C" void kernel_launch(void* const* d_in, const int* in_sizes, int n_in,
                              void* d_out, int out_size) {
    const float* x    = (const float*)d_in[0];
    const float* W    = (const float*)d_in[1];
    const float* bias = (const float*)d_in[2];
    const int*   idx  = (const int*)d_in[3];
    float*       out  = (float*)d_out;

    cudaFuncSetAttribute(embed_bigraph_kernel,
                         cudaFuncAttributeMaxDynamicSharedMemorySize, SMEM_BYTES);

    build_xT2_kernel<<<dim3(MM / 8, CC / 8), 128>>>(x);
    embed_bigraph_kernel<<<LL, 128, SMEM_BYTES>>>(W, bias, idx, out);
}

// round 8
// speedup vs baseline: 1.4639x; 1.4639x over previous
#include <cuda_runtime.h>
#include <cuda_bf16.h>
#include <cstdint>

#define NN 64
#define CC 32
#define MM 4000
#define LL 2000
#define DD 16
#define OO 32

// ---------------------------------------------------------------------------
// Global scratch
// xTb[m][row][c]: row = 2n + part (part 0 = hi bf16, 1 = lo bf16), c in [0,32)
// ---------------------------------------------------------------------------
__device__ __align__(256) __nv_bfloat16 g_xTb[(size_t)MM * 128 * 32];   // 32.8 MB
__device__ __align__(256) float g_out_ln[(size_t)LL * 64 * 32];         // 16.4 MB

// SMEM map: rows padded to 272 B (17 granules -> conflict-free ldmatrix)
#define A_STRIDE 272
#define A_BUF (128 * A_STRIDE)          // 34816
#define B_BUF (64 * A_STRIDE)           // 17408
#define OFF_A0 0u
#define OFF_A1 34816u
#define OFF_B0 69632u
#define OFF_B1 87040u
#define SMEM_SZ 104448

__device__ __forceinline__ uint32_t smem_u32_of(const void* p) {
    uint32_t a;
    asm("{ .reg .u64 t; cvta.to.shared.u64 t, %1; cvt.u32.u64 %0, t; }"
        : "=r"(a) : "l"(p));
    return a;
}

// bf16 hi/lo split of a pair (v0 -> low half, v1 -> high half)
__device__ __forceinline__ void split_pair(float v0, float v1,
                                           uint32_t& h2, uint32_t& l2) {
    asm("cvt.rn.bf16x2.f32 %0, %1, %2;" : "=r"(h2) : "f"(v1), "f"(v0));
    float h0 = __uint_as_float(h2 << 16);
    float h1 = __uint_as_float(h2 & 0xffff0000u);
    float r0 = v0 - h0, r1 = v1 - h1;
    asm("cvt.rn.bf16x2.f32 %0, %1, %2;" : "=r"(l2) : "f"(r1), "f"(r0));
}

// ---------------------------------------------------------------------------
// Kernel 1: x[n][c][m] -> g_xTb[m][2n|2n+1][c]  (hi/lo bf16)
// grid (125, 64), block 256
// ---------------------------------------------------------------------------
__global__ void build_xTb_kernel(const float* __restrict__ x) {
    __shared__ float tile[32 * 33];
    int m0 = blockIdx.x * 32;
    int n  = blockIdx.y;
    int tid = threadIdx.x;
#pragma unroll
    for (int it = 0; it < 4; it++) {
        int t = tid + 256 * it;
        int c = t >> 5, mi = t & 31;
        tile[c * 33 + mi] = x[((size_t)n * CC + c) * MM + m0 + mi];
    }
    __syncthreads();
    int mi = tid >> 3, c4 = tid & 7;
    float v0 = tile[(c4 * 4 + 0) * 33 + mi];
    float v1 = tile[(c4 * 4 + 1) * 33 + mi];
    float v2 = tile[(c4 * 4 + 2) * 33 + mi];
    float v3 = tile[(c4 * 4 + 3) * 33 + mi];
    uint32_t h2a, l2a, h2b, l2b;
    split_pair(v0, v1, h2a, l2a);
    split_pair(v2, v3, h2b, l2b);
    char* base = (char*)g_xTb + ((size_t)(m0 + mi) * 128 + 2 * n) * 64 + c4 * 8;
    *(uint2*)base        = make_uint2(h2a, h2b);
    *(uint2*)(base + 64) = make_uint2(l2a, l2b);
}

// ---------------------------------------------------------------------------
// Kernel 2: per-l gather-GEMM on legacy tensor cores (mma.sync bf16)
// ---------------------------------------------------------------------------
struct B8 { float4 a[4], b[4]; };

__device__ __forceinline__ void stage_A(uint32_t dstb, const int* __restrict__ idx,
                                        int l, int ch, int tid) {
#pragma unroll
    for (int tt = 0; tt < 16; tt++) {
        int dd = tt >> 2;                           // constant per tt
        int m  = __ldg(idx + l * DD + ch * 4 + dd);
        int r  = ((tid >> 2) + 32 * tt) & 127;
        int g  = tid & 3;
        const char* src = (const char*)g_xTb + ((size_t)m * 128 + r) * 64 + g * 16;
        uint32_t dst = dstb + (uint32_t)(r * A_STRIDE + dd * 64 + g * 16);
        asm volatile("cp.async.cg.shared.global [%0], [%1], 16;"
                     :: "r"(dst), "l"(src));
    }
    asm volatile("cp.async.commit_group;" ::: "memory");
}

__device__ __forceinline__ void ldg_B(B8& r, const float* __restrict__ W,
                                      int l, int ch, int tid) {
#pragma unroll
    for (int t = 0; t < 4; t++) {
        int q = tid + 128 * t;                      // q < 512
        int o = q >> 4, cp = q & 15;
        const float4* p = (const float4*)(W + ((size_t)l * 1024 + o * 32 + 2 * cp) * 16
                                          + ch * 4);
        r.a[t] = p[0];          // c = 2cp
        r.b[t] = p[4];          // c = 2cp+1
    }
}

__device__ __forceinline__ void sts_B(char* bb, const B8& r, int tid) {
#pragma unroll
    for (int t = 0; t < 4; t++) {
        int q = tid + 128 * t;
        int o = q >> 4, cp = q & 15;
        const float* va = (const float*)&r.a[t];
        const float* vb = (const float*)&r.b[t];
#pragma unroll
        for (int dd = 0; dd < 4; dd++) {
            uint32_t h2, l2;
            split_pair(va[dd], vb[dd], h2, l2);
            char* p = bb + o * A_STRIDE + dd * 64 + cp * 4;
            *(uint32_t*)p                       = h2;   // rows 0..31  = W_hi
            *(uint32_t*)(p + 32 * A_STRIDE)     = l2;   // rows 32..63 = W_lo
        }
    }
}

#define LDMX4(r, addr) \
    asm volatile("ldmatrix.sync.aligned.m8n8.x4.shared.b16 {%0,%1,%2,%3}, [%4];" \
                 : "=r"((r)[0]), "=r"((r)[1]), "=r"((r)[2]), "=r"((r)[3]) \
                 : "r"(addr))

#define LDS32(r, addr) \
    asm volatile("ld.shared.b32 %0, [%1];" : "=r"(r) : "r"(addr))

#define MMA16816(d, a, b) \
    asm volatile("mma.sync.aligned.m16n8k16.row.col.f32.bf16.bf16.f32 " \
                 "{%0,%1,%2,%3}, {%4,%5,%6,%7}, {%8,%9}, {%0,%1,%2,%3};" \
                 : "+f"((d)[0]), "+f"((d)[1]), "+f"((d)[2]), "+f"((d)[3]) \
                 : "r"((a)[0]), "r"((a)[1]), "r"((a)[2]), "r"((a)[3]), \
                   "r"((b)[0]), "r"((b)[1]))

__device__ __forceinline__ void compute_chunk(uint32_t As, uint32_t Bs,
                                              int wid, int lane,
                                              float acc[2][8][4]) {
    const uint32_t a_row = (lane & 7) + ((lane >> 3) & 1) * 8;
    const uint32_t a0b = As + (32 * wid + a_row) * A_STRIDE + (lane >> 4) * 16;
    const uint32_t a1b = a0b + 16 * A_STRIDE;
    const uint32_t bbs = Bs + (lane >> 2) * A_STRIDE + (lane & 3) * 4;
#pragma unroll
    for (int ks = 0; ks < 8; ks++) {
        uint32_t a0[4], a1[4];
        LDMX4(a0, a0b + ks * 32);
        LDMX4(a1, a1b + ks * 32);
        uint32_t bb[8][2];
#pragma unroll
        for (int nt = 0; nt < 8; nt++) {
            uint32_t ba = bbs + nt * (8 * A_STRIDE) + ks * 32;
            LDS32(bb[nt][0], ba);
            LDS32(bb[nt][1], ba + 16);
        }
#pragma unroll
        for (int nt = 0; nt < 8; nt++) {
            MMA16816(acc[0][nt], a0, bb[nt]);
            MMA16816(acc[1][nt], a1, bb[nt]);
        }
    }
}

__global__ __launch_bounds__(128, 2)
void gemm_kernel(const float* __restrict__ W, const int* __restrict__ idx) {
    extern __shared__ char sm[];
    const uint32_t sb = smem_u32_of(sm);
    const int tid = threadIdx.x, wid = tid >> 5, lane = tid & 31;

    B8 br;
    for (int l = blockIdx.x; l < LL; l += gridDim.x) {
        float acc[2][8][4];
#pragma unroll
        for (int t = 0; t < 2; t++)
#pragma unroll
            for (int nt = 0; nt < 8; nt++)
#pragma unroll
                for (int r = 0; r < 4; r++) acc[t][nt][r] = 0.0f;

        // prologue: chunk 0
        stage_A(sb + OFF_A0, idx, l, 0, tid);
        ldg_B(br, W, l, 0, tid);
        asm volatile("cp.async.wait_group 0;" ::: "memory");
        sts_B(sm + OFF_B0, br, tid);
        __syncthreads();

#pragma unroll
        for (int ch = 0; ch < 4; ch++) {
            const int s = ch & 1;
            if (ch < 3) {
                stage_A(sb + (s ? OFF_A0 : OFF_A1), idx, l, ch + 1, tid);
                ldg_B(br, W, l, ch + 1, tid);
            }
            compute_chunk(sb + (s ? OFF_A1 : OFF_A0),
                          sb + (s ? OFF_B1 : OFF_B0), wid, lane, acc);
            if (ch < 3) {
                asm volatile("cp.async.wait_group 0;" ::: "memory");
                sts_B(sm + (s ? OFF_B0 : OFF_B1), br, tid);
                __syncthreads();
            }
        }

        // epilogue: fold q (cols o vs o+32), fold hi/lo row pairs, store
#pragma unroll
        for (int t = 0; t < 2; t++)
#pragma unroll
            for (int nt = 0; nt < 4; nt++)
#pragma unroll
                for (int r = 0; r < 4; r++)
                    acc[t][nt][r] += acc[t][nt + 4][r];

        float v[2][4][4];
#pragma unroll
        for (int t = 0; t < 2; t++)
#pragma unroll
            for (int nt = 0; nt < 4; nt++)
#pragma unroll
                for (int r = 0; r < 4; r++)
                    v[t][nt][r] = acc[t][nt][r]
                        + __shfl_xor_sync(0xffffffffu, acc[t][nt][r], 4);

        if ((lane & 4) == 0) {
            const int ghalf = lane >> 3;            // g/2 for even g
            const int tig2  = (lane & 3) * 2;
#pragma unroll
            for (int t = 0; t < 2; t++)
#pragma unroll
                for (int u = 0; u < 2; u++) {
                    int n = wid * 16 + 8 * t + 4 * u + ghalf;
                    float* op = g_out_ln + ((size_t)l * 64 + n) * 32;
#pragma unroll
                    for (int nt = 0; nt < 4; nt++) {
                        int o = nt * 8 + tig2;
                        *(float2*)(op + o) = make_float2(v[t][nt][2 * u],
                                                         v[t][nt][2 * u + 1]);
                    }
                }
        }
        __syncthreads();
    }
}

// ---------------------------------------------------------------------------
// Kernel 3: g_out_ln[l][p] + bias -> out[p][l]   (p = n*32 + o, o = p & 31)
// grid (64, 63), block (32, 8)
// ---------------------------------------------------------------------------
__global__ void out_transpose_kernel(const float* __restrict__ bias,
                                     float* __restrict__ out) {
    __shared__ float t[32][33];
    int p0 = blockIdx.x * 32, l0 = blockIdx.y * 32;
    int tx = threadIdx.x, ty = threadIdx.y;
#pragma unroll
    for (int j = 0; j < 32; j += 8) {
        int l = l0 + ty + j;
        if (l < LL)
            t[ty + j][tx] = g_out_ln[(size_t)l * 2048 + p0 + tx]
                          + __ldg(bias + l * OO + (tx & 31));
    }
    __syncthreads();
#pragma unroll
    for (int j = 0; j < 32; j += 8) {
        int l = l0 + tx, p = p0 + ty + j;
        if (l < LL) out[(size_t)p * LL + l] = t[tx][ty + j];
    }
}

// ---------------------------------------------------------------------------
// Launch
// ---------------------------------------------------------------------------
extern "C" void kernel_launch(void* const* d_in, const int* in_sizes, int n_in,
                              void* d_out, int out_size) {
    const float* x    = (const float*)d_in[0];
    const float* W    = (const float*)d_in[1];
    const float* bias = (const float*)d_in[2];
    const int*   idx  = (const int*)d_in[3];
    float*       out  = (float*)d_out;

    cudaFuncSetAttribute(gemm_kernel,
                         cudaFuncAttributeMaxDynamicSharedMemorySize, SMEM_SZ);

    build_xTb_kernel<<<dim3(MM / 32, NN), 256>>>(x);
    gemm_kernel<<<296, 128, SMEM_SZ>>>(W, idx);
    out_transpose_kernel<<<dim3(64, 63), dim3(32, 8)>>>(bias, out);
}